// round 16
// baseline (speedup 1.0000x reference)
#include <cuda_runtime.h>
#include <cstdint>

#define BB 4
#define NN 8192
#define CIN 64
#define CC 128
#define MM 2048
#define KK 32
#define LL 2

typedef unsigned long long ull;

// ---------------- scratch (static device globals; no allocation) ----------------
__device__ float  g_feats[BB*NN*CC];
__device__ float  g_xf[BB*MM*CC];
__device__ float  g_t1[BB*MM*CC];
__device__ float  g_t2[BB*MM*CC];
__device__ float  g_centbuf[BB*MM*3];
__device__ int    g_nbr1[BB*MM*KK];
__device__ int    g_nbr2[BB*MM*KK];
__device__ double g_sumS[7*CC], g_sqsS[7*CC];          // 7 BN stat slots
__device__ double g_m1a[3], g_m2a[6], g_m1b[3], g_m2b[6];

// ---------------- packed f32x2 helpers -------------------------------------------
__device__ __forceinline__ ull pk2(float a, float b) {
    ull r; asm("mov.b64 %0,{%1,%2};" : "=l"(r) : "f"(a), "f"(b)); return r;
}
__device__ __forceinline__ void upk2u(ull v, unsigned& a, unsigned& b) {
    asm("mov.b64 {%0,%1},%2;" : "=r"(a), "=r"(b) : "l"(v));
}
__device__ __forceinline__ ull fma2(ull a, ull b, ull c) {
    ull r; asm("fma.rn.f32x2 %0,%1,%2,%3;" : "=l"(r) : "l"(a), "l"(b), "l"(c)); return r;
}
// warp collectives in ONE instruction (sm_80+)
__device__ __forceinline__ unsigned redux_max(unsigned v) {
    unsigned r; asm("redux.sync.max.u32 %0, %1, 0xffffffff;" : "=r"(r) : "r"(v));
    return r;
}
__device__ __forceinline__ unsigned redux_min(unsigned v) {
    unsigned r; asm("redux.sync.min.u32 %0, %1, 0xffffffff;" : "=r"(r) : "r"(v));
    return r;
}
__device__ __forceinline__ unsigned umin2(unsigned a, unsigned b) { return a < b ? a : b; }
__device__ __forceinline__ unsigned umax2(unsigned a, unsigned b) { return a > b ? a : b; }

// ---------------- inline BN affine reconstruction --------------------------------
__device__ __forceinline__ void bn_aff(const double* __restrict__ sum,
        const double* __restrict__ sqs, const float* __restrict__ gam,
        const float* __restrict__ bet, double inv, int c, float& sc, float& sh) {
    double m = sum[c] * inv;
    double v = sqs[c] * inv - m * m;
    float s = gam[c] * rsqrtf((float)v + 1e-5f);
    sc = s; sh = fmaf(-(float)m, s, bet[c]);
}
__device__ __forceinline__ void bn_aff3(const double* __restrict__ m1,
        const double* __restrict__ m2, const float* __restrict__ W3,
        const float* __restrict__ gam, const float* __restrict__ bet,
        double inv, int c, float& sc, float& sh) {
    double w0 = W3[3*c], w1 = W3[3*c+1], w2 = W3[3*c+2];
    double mean = (m1[0]*w0 + m1[1]*w1 + m1[2]*w2) * inv;
    double e2 = (w0*w0*m2[0] + w1*w1*m2[3] + w2*w2*m2[5]
               + 2.0*(w0*w1*m2[1] + w0*w2*m2[2] + w1*w2*m2[4])) * inv;
    double var = e2 - mean*mean;
    float s = gam[c] * rsqrtf((float)var + 1e-5f);
    sc = s; sh = fmaf(-(float)mean, s, bet[c]);
}

// ---------------- init: zero all accumulators -------------------------------------
__global__ void init_kernel() {
    int t = threadIdx.x;
    for (int i = t; i < 7*CC; i += 1024) { g_sumS[i] = 0.0; g_sqsS[i] = 0.0; }
    if (t < 3) { g_m1a[t] = 0.0; g_m1b[t] = 0.0; }
    if (t < 6) { g_m2a[t] = 0.0; g_m2b[t] = 0.0; }
}

// ------- FPS: exact jax-scan; FFMA2 + integer min/max + paired-REDUX argmax ------
// smem point cache: post-reduction broadcast is LDS instead of LDG.
__global__ void __launch_bounds__(1024) fps_kernel(const float* __restrict__ pos,
                                                   float* __restrict__ cent) {
    extern __shared__ float sP[];              // [NN*3] raw xyz cache
    __shared__ ull red2[2][32];                // per-warp (maxval<<32)|minidx
    int b = blockIdx.x, t = threadIdx.x;
    int lane = t & 31, wid = t >> 5;
    const float* P = pos + (size_t)b * NN * 3;

    // fill smem cache with float4 loads (98304 B = 6144 float4)
    {
        const float4* P4 = (const float4*)P;
        float4* S4 = (float4*)sP;
        for (int i = t; i < (NN*3)/4; i += 1024) S4[i] = P4[i];
    }

    // 8 strided points per thread (indices t + q*1024), packed into f32x2 pairs
    ull pxp[4], pyp[4], pzp[4];
    unsigned dd[8];                            // distance bit patterns (monotone)
#pragma unroll
    for (int jp = 0; jp < 4; jp++) {
        int i0 = t + (2*jp) * 1024;
        int i1 = t + (2*jp+1) * 1024;
        pxp[jp] = pk2(P[i0*3],   P[i1*3]);
        pyp[jp] = pk2(P[i0*3+1], P[i1*3+1]);
        pzp[jp] = pk2(P[i0*3+2], P[i1*3+2]);
        dd[2*jp] = __float_as_uint(1e10f); dd[2*jp+1] = __float_as_uint(1e10f);
    }

    float lx = P[0], ly = P[1], lz = P[2];
    if (t == 0) {
        float* c0 = cent + (size_t)b*MM*3;
        c0[0] = lx; c0[1] = ly; c0[2] = lz;
    }
    const ull ONE2 = pk2(1.0f, 1.0f);
    __syncthreads();                           // smem cache ready

    for (int m = 1; m < MM; m++) {
        int p = m & 1;
        ull nlx2 = pk2(-lx, -lx), nly2 = pk2(-ly, -ly), nlz2 = pk2(-lz, -lz);
#pragma unroll
        for (int jp = 0; jp < 4; jp++) {
            // FFMA2 chain bit-identical to scalar rn sequence:
            // dx=rn(px-lx); sx=rn(dx^2); s=rn(rn(sx+sy)+sz); dd=min(dd,s)
            ull dx = fma2(pxp[jp], ONE2, nlx2);
            ull dy = fma2(pyp[jp], ONE2, nly2);
            ull dz = fma2(pzp[jp], ONE2, nlz2);
            ull sx = fma2(dx, dx, 0ull);
            ull sy = fma2(dy, dy, 0ull);
            ull sz = fma2(dz, dz, 0ull);
            ull s  = fma2(sz, ONE2, fma2(sy, ONE2, sx));
            unsigned u0, u1; upk2u(s, u0, u1);
            dd[2*jp]   = umin2(dd[2*jp],   u0);   // IMNMX, exact (bits monotone)
            dd[2*jp+1] = umin2(dd[2*jp+1], u1);
        }
        // thread-local max value (integer max tree)
        unsigned bm = dd[0];
#pragma unroll
        for (int q = 1; q < 8; q++) bm = umax2(bm, dd[q]);
        // warp max value: one REDUX
        unsigned wmax = redux_max(bm);
        // only threads attaining the warp max scan for their smallest index (rare)
        unsigned cand = 0xffffffffu;
        if (bm == wmax) {
#pragma unroll
            for (int q = 7; q >= 0; q--)
                if (dd[q] == wmax) cand = (unsigned)(t + (q << 10));
        }
        unsigned wmin = redux_min(cand);
        if (lane == 0) red2[p][wid] = ((ull)wmax << 32) | wmin;
        __syncthreads();                            // the ONLY barrier
        // block phase (redundant in every warp): one LDS.64, then two REDUX
        ull wv = red2[p][lane];
        unsigned v32 = (unsigned)(wv >> 32);
        unsigned i32 = (unsigned)wv;
        unsigned bvb = redux_max(v32);
        unsigned candb = (v32 == bvb) ? i32 : 0xffffffffu;
        int sel = (int)redux_min(candb);
        lx = sP[sel*3]; ly = sP[sel*3+1]; lz = sP[sel*3+2];   // LDS broadcast
        if (t == 0) {
            float* co = cent + ((size_t)b*MM + m) * 3;
            co[0] = lx; co[1] = ly; co[2] = lz;
        }
    }
}

// ------- register-tiled GEMM: Y[r,o] = sum_c A[r,c]*W[o,c] ----------------------
template <int CK>
__global__ void __launch_bounds__(128) gemm_tiled(const float* __restrict__ A,
        const float* __restrict__ W, float* __restrict__ Y,
        double* __restrict__ oSum, double* __restrict__ oSqs,
        const double* __restrict__ pSum, const double* __restrict__ pSqs,
        const float* __restrict__ pGam, const float* __restrict__ pBet, double pInv) {
    __shared__ float As[16][68];
    __shared__ float Ws[16][132];
    __shared__ float psc[128], psh[128];
    __shared__ float sred[8][128];
    int t = threadIdx.x;
    int tx = t & 15, ty = t >> 4;
    if (pSum) bn_aff(pSum, pSqs, pGam, pBet, pInv, t, psc[t], psh[t]);
    size_t m0 = (size_t)blockIdx.x * 64;

    float acc[8][8];
#pragma unroll
    for (int i = 0; i < 8; i++)
#pragma unroll
        for (int j = 0; j < 8; j++) acc[i][j] = 0.f;

    for (int k0 = 0; k0 < CK; k0 += 16) {
        __syncthreads();
        {
            int f = t & 3;
            int cbase = k0 + f*4;
#pragma unroll
            for (int p = 0; p < 2; p++) {
                int m = p*32 + (t >> 2);
                float4 v = *(const float4*)(A + (m0 + m)*CK + cbase);
                if (pSum) {
                    v.x = fmaxf(fmaf(v.x, psc[cbase+0], psh[cbase+0]), 0.f);
                    v.y = fmaxf(fmaf(v.y, psc[cbase+1], psh[cbase+1]), 0.f);
                    v.z = fmaxf(fmaf(v.z, psc[cbase+2], psh[cbase+2]), 0.f);
                    v.w = fmaxf(fmaf(v.w, psc[cbase+3], psh[cbase+3]), 0.f);
                }
                As[f*4+0][m] = v.x; As[f*4+1][m] = v.y;
                As[f*4+2][m] = v.z; As[f*4+3][m] = v.w;
            }
        }
        {
            const float* ws = W + (size_t)t*CK + k0;
            float4 w0 = *(const float4*)(ws);
            float4 w1 = *(const float4*)(ws+4);
            float4 w2 = *(const float4*)(ws+8);
            float4 w3 = *(const float4*)(ws+12);
            Ws[ 0][t]=w0.x; Ws[ 1][t]=w0.y; Ws[ 2][t]=w0.z; Ws[ 3][t]=w0.w;
            Ws[ 4][t]=w1.x; Ws[ 5][t]=w1.y; Ws[ 6][t]=w1.z; Ws[ 7][t]=w1.w;
            Ws[ 8][t]=w2.x; Ws[ 9][t]=w2.y; Ws[10][t]=w2.z; Ws[11][t]=w2.w;
            Ws[12][t]=w3.x; Ws[13][t]=w3.y; Ws[14][t]=w3.z; Ws[15][t]=w3.w;
        }
        __syncthreads();
#pragma unroll
        for (int k = 0; k < 16; k++) {
            float a[8], w[8];
            *(float4*)&a[0] = *(const float4*)&As[k][ty*8];
            *(float4*)&a[4] = *(const float4*)&As[k][ty*8+4];
            *(float4*)&w[0] = *(const float4*)&Ws[k][tx*8];
            *(float4*)&w[4] = *(const float4*)&Ws[k][tx*8+4];
#pragma unroll
            for (int i = 0; i < 8; i++)
#pragma unroll
                for (int j = 0; j < 8; j++)
                    acc[i][j] = fmaf(a[i], w[j], acc[i][j]);
        }
    }

#pragma unroll
    for (int i = 0; i < 8; i++) {
        int m = ty*8 + i;
        float* dst = Y + (m0 + m)*128 + tx*8;
        *(float4*)(dst)     = make_float4(acc[i][0], acc[i][1], acc[i][2], acc[i][3]);
        *(float4*)(dst + 4) = make_float4(acc[i][4], acc[i][5], acc[i][6], acc[i][7]);
    }

    float s_[8], q_[8];
#pragma unroll
    for (int j = 0; j < 8; j++) {
        float s = 0.f, q = 0.f;
#pragma unroll
        for (int i = 0; i < 8; i++) {
            s += acc[i][j];
            q = fmaf(acc[i][j], acc[i][j], q);
        }
        s_[j] = s; q_[j] = q;
    }
    __syncthreads();
#pragma unroll
    for (int j = 0; j < 8; j++) sred[ty][tx*8+j] = s_[j];
    __syncthreads();
    float bs = 0.f;
#pragma unroll
    for (int r = 0; r < 8; r++) bs += sred[r][t];
    __syncthreads();
#pragma unroll
    for (int j = 0; j < 8; j++) sred[ty][tx*8+j] = q_[j];
    __syncthreads();
    float bq = 0.f;
#pragma unroll
    for (int r = 0; r < 8; r++) bq += sred[r][t];
    atomicAdd(&oSum[t], (double)bs);
    atomicAdd(&oSqs[t], (double)bq);
}

// ---------------- ball query with smem point cache (exact thresholds) ------------
__global__ void __launch_bounds__(256) bq_kernel(const float* __restrict__ q,
        const float* __restrict__ pts, int np, float r2, int* __restrict__ nbr) {
    extern __shared__ float sp[];
    float* sx = sp; float* sy = sp + np; float* sz = sp + 2*np;
    int gw0 = blockIdx.x * 8;
    int b = gw0 >> 11;
    const float* P = pts + (size_t)b * np * 3;
    for (int idx = threadIdx.x; idx < np*3; idx += 256) {
        float v = P[idx];
        int pt = idx / 3, d = idx - pt*3;
        sp[d*np + pt] = v;
    }
    __syncthreads();
    int w = threadIdx.x >> 5, lane = threadIdx.x & 31;
    int gw = gw0 + w;
    const float* Q = q + (size_t)gw * 3;
    float qx = Q[0], qy = Q[1], qz = Q[2];
    int cnt = 0, first = 0;
    for (int base = 0; base < np; base += 32) {
        int i = base + lane;
        float dx = __fadd_rn(qx, -sx[i]), dy = __fadd_rn(qy, -sy[i]), dz = __fadd_rn(qz, -sz[i]);
        float d2 = __fadd_rn(__fadd_rn(__fmul_rn(dx,dx), __fmul_rn(dy,dy)),
                             __fmul_rn(dz,dz));
        bool pred = d2 < r2;
        unsigned mask = __ballot_sync(0xffffffffu, pred);
        if (cnt == 0 && mask) first = base + __ffs(mask) - 1;
        if (pred) {
            int pos = cnt + __popc(mask & ((1u << lane) - 1u));
            if (pos < KK) nbr[(size_t)gw*KK + pos] = i;
        }
        cnt += __popc(mask);
        if (cnt >= KK) break;
    }
    for (int k = cnt + lane; k < KK; k += 32) nbr[(size_t)gw*KK + k] = first;
}

// ---------------- 3-dim offset moments ------------------------------------------
__global__ void moments_kernel(const int* __restrict__ nbr, const float* __restrict__ pts,
                               const float* __restrict__ cent, float R, int np,
                               double* __restrict__ m1, double* __restrict__ m2) {
    int idx = blockIdx.x * blockDim.x + threadIdx.x;
    int bm = idx / KK;
    int b = bm >> 11;
    int j = nbr[idx];
    float cx = cent[(size_t)bm*3], cy = cent[(size_t)bm*3+1], cz = cent[(size_t)bm*3+2];
    const float* p = pts + ((size_t)b*np + j) * 3;
    float v0 = (p[0]-cx)/R, v1 = (p[1]-cy)/R, v2 = (p[2]-cz)/R;
    double a[9] = { v0, v1, v2,
                    (double)v0*v0, (double)v0*v1, (double)v0*v2,
                    (double)v1*v1, (double)v1*v2, (double)v2*v2 };
#pragma unroll
    for (int v = 0; v < 9; v++) {
        double x = a[v];
        for (int off = 16; off; off >>= 1) x += __shfl_down_sync(0xffffffffu, x, off);
        a[v] = x;
    }
    if ((threadIdx.x & 31) == 0) {
        atomicAdd(&m1[0], a[0]); atomicAdd(&m1[1], a[1]); atomicAdd(&m1[2], a[2]);
        atomicAdd(&m2[0], a[3]); atomicAdd(&m2[1], a[4]); atomicAdd(&m2[2], a[5]);
        atomicAdd(&m2[3], a[6]); atomicAdd(&m2[4], a[7]); atomicAdd(&m2[5], a[8]);
    }
}

// ------- fused gather(+inline feats BN-relu) + pos-conv-BN-relu + max over K -----
__global__ void __launch_bounds__(128) agg_kernel(const float* __restrict__ feats, int np,
        const float* __restrict__ pts, const float* __restrict__ cent,
        const int* __restrict__ nbr, const float* __restrict__ W3, float R,
        const double* __restrict__ fSum, const double* __restrict__ fSqs,
        const float* __restrict__ fGam, const float* __restrict__ fBet, double fInv,
        const double* __restrict__ m1, const double* __restrict__ m2,
        const float* __restrict__ pGam, const float* __restrict__ pBet, double mInv,
        float* __restrict__ out) {
    int bm = blockIdx.x;
    int b = bm >> 11;
    int c = threadIdx.x;
    __shared__ int   sj[KK];
    __shared__ float sg[KK][3];
    if (c < KK) {
        int j = nbr[(size_t)bm*KK + c];
        sj[c] = j;
        float cx = cent[(size_t)bm*3], cy = cent[(size_t)bm*3+1], cz = cent[(size_t)bm*3+2];
        const float* p = pts + ((size_t)b*np + j) * 3;
        sg[c][0] = (p[0]-cx)/R; sg[c][1] = (p[1]-cy)/R; sg[c][2] = (p[2]-cz)/R;
    }
    float asc, ash, sc, sh;
    bn_aff(fSum, fSqs, fGam, fBet, fInv, c, asc, ash);
    bn_aff3(m1, m2, W3, pGam, pBet, mInv, c, sc, sh);
    float w0 = W3[3*c], w1 = W3[3*c+1], w2 = W3[3*c+2];
    __syncthreads();
    const float* F = feats + (size_t)b * np * 128 + c;
    float acc = -3.4e38f;
#pragma unroll
    for (int k = 0; k < KK; k++) {
        float dot = fmaf(w2, sg[k][2], fmaf(w1, sg[k][1], w0 * sg[k][0]));
        float pev = fmaxf(fmaf(sc, dot, sh), 0.f);
        float raw = F[(size_t)sj[k] * 128];
        float gf = fmaxf(fmaf(raw, asc, ash), 0.f);
        acc = fmaxf(acc, gf + pev);
    }
    out[(size_t)bm*128 + c] = acc;
}

// ------ residual: relu( relu(affA(fi)) + affC(y) ), affines inlined --------------
__global__ void resid_kernel(const float* __restrict__ fi, const float* __restrict__ y,
        const double* __restrict__ aSum, const double* __restrict__ aSqs,
        const float* __restrict__ aGam, const float* __restrict__ aBet,
        const double* __restrict__ cSum, const double* __restrict__ cSqs,
        const float* __restrict__ cGam, const float* __restrict__ cBet,
        double inv, float* __restrict__ out, int ntot) {
    int i = blockIdx.x * blockDim.x + threadIdx.x;
    if (i < ntot) {
        int c = i & 127;
        float sa, ha, scc, hc;
        bn_aff(aSum, aSqs, aGam, aBet, inv, c, sa, ha);
        bn_aff(cSum, cSqs, cGam, cBet, inv, c, scc, hc);
        float f = fmaxf(fmaf(fi[i], sa, ha), 0.f);
        out[i] = fmaxf(f + fmaf(y[i], scc, hc), 0.f);
    }
}

// =================================================================================
extern "C" void kernel_launch(void* const* d_in, const int* in_sizes, int n_in,
                              void* d_out, int out_size) {
    const float* pos  = (const float*)d_in[0];
    const float* x    = (const float*)d_in[1];
    const float* W_x  = (const float*)d_in[2];
    const float* gx   = (const float*)d_in[3];
    const float* bx   = (const float*)d_in[4];
    const float* W_ps = (const float*)d_in[5];
    const float* gps  = (const float*)d_in[6];
    const float* bps  = (const float*)d_in[7];
    const float* W_pe = (const float*)d_in[8];
    const float* gpe  = (const float*)d_in[9];
    const float* bpe  = (const float*)d_in[10];
    const float* W1   = (const float*)d_in[11];
    const float* g1   = (const float*)d_in[12];
    const float* b1   = (const float*)d_in[13];
    const float* W2a  = (const float*)d_in[14];
    const float* g2a  = (const float*)d_in[15];
    const float* b2a  = (const float*)d_in[16];
    const float* W2b  = (const float*)d_in[17];
    const float* g2b  = (const float*)d_in[18];
    const float* b2b  = (const float*)d_in[19];

    float* out = (float*)d_out;
    float* cent; float* xf_out; float* centbuf;
    cudaGetSymbolAddress((void**)&centbuf, g_centbuf);
    if (out_size == BB*MM*3 + BB*MM*CC) { cent = out; xf_out = out + BB*MM*3; }
    else                                { cent = centbuf; xf_out = out; }

    float *feats, *xf, *t1, *t2;
    int *nbr1, *nbr2;
    double *sumS, *sqsS, *m1a, *m2a, *m1b, *m2b;
    cudaGetSymbolAddress((void**)&feats, g_feats);
    cudaGetSymbolAddress((void**)&xf,    g_xf);
    cudaGetSymbolAddress((void**)&t1,    g_t1);
    cudaGetSymbolAddress((void**)&t2,    g_t2);
    cudaGetSymbolAddress((void**)&nbr1,  g_nbr1);
    cudaGetSymbolAddress((void**)&nbr2,  g_nbr2);
    cudaGetSymbolAddress((void**)&sumS,  g_sumS);
    cudaGetSymbolAddress((void**)&sqsS,  g_sqsS);
    cudaGetSymbolAddress((void**)&m1a,   g_m1a);
    cudaGetSymbolAddress((void**)&m2a,   g_m2a);
    cudaGetSymbolAddress((void**)&m1b,   g_m1b);
    cudaGetSymbolAddress((void**)&m2b,   g_m2b);

    static cudaStream_t s1 = nullptr, s2 = nullptr;
    static cudaEvent_t eFork, eXmlp, eFps, eS2;
    if (!s1) {
        cudaStreamCreateWithFlags(&s1, cudaStreamNonBlocking);
        cudaStreamCreateWithFlags(&s2, cudaStreamNonBlocking);
        cudaEventCreateWithFlags(&eFork, cudaEventDisableTiming);
        cudaEventCreateWithFlags(&eXmlp, cudaEventDisableTiming);
        cudaEventCreateWithFlags(&eFps,  cudaEventDisableTiming);
        cudaEventCreateWithFlags(&eS2,   cudaEventDisableTiming);
    }

    const int smemBQ1 = NN * 3 * 4;
    const int smemBQ2 = MM * 3 * 4;
    const int smemFPS = NN * 3 * 4;
    cudaFuncSetAttribute(bq_kernel,  cudaFuncAttributeMaxDynamicSharedMemorySize, smemBQ1);
    cudaFuncSetAttribute(fps_kernel, cudaFuncAttributeMaxDynamicSharedMemorySize, smemFPS);

    const double invN = 1.0 / (BB*NN);
    const double invM = 1.0 / (BB*MM);
    const double invK = 1.0 / (BB*MM*KK);

    // init, then fork x_mlp chain onto s1 while FPS runs on default
    init_kernel<<<1, 1024>>>();
    cudaEventRecord(eFork, 0);
    cudaStreamWaitEvent(s1, eFork, 0);

    fps_kernel<<<BB, 1024, smemFPS>>>(pos, cent);

    gemm_tiled<CIN><<<(BB*NN)/64, 128, 0, s1>>>(x, W_x, feats,
        sumS + 0*CC, sqsS + 0*CC, nullptr, nullptr, nullptr, nullptr, 0.0);
    cudaEventRecord(eXmlp, s1);

    // fork bq2+momentsB onto s2 (needs cent only)
    cudaEventRecord(eFps, 0);
    cudaStreamWaitEvent(s2, eFps, 0);
    bq_kernel<<<(BB*MM)/8, 256, smemBQ2, s2>>>(cent, cent, MM, 0.04f, nbr2);
    moments_kernel<<<(BB*MM*KK)/256, 256, 0, s2>>>(nbr2, cent, cent, 0.2f, MM, m1b, m2b);
    cudaEventRecord(eS2, s2);

    // default: bq1 + momentsA
    bq_kernel<<<(BB*MM)/8, 256, smemBQ1>>>(cent, pos, NN, 0.01f, nbr1);
    moments_kernel<<<(BB*MM*KK)/256, 256>>>(nbr1, pos, cent, 0.1f, NN, m1a, m2a);

    cudaStreamWaitEvent(0, eS2, 0);
    cudaStreamWaitEvent(0, eXmlp, 0);

    // stage-1 aggregation (all BN affines inlined) -> xf
    agg_kernel<<<BB*MM, 128>>>(feats, NN, pos, cent, nbr1, W_ps, 0.1f,
        sumS + 0*CC, sqsS + 0*CC, gx, bx, invN,
        m1a, m2a, gps, bps, invK, xf);

    // InvResMLP blocks
    for (int i = 0; i < LL; i++) {
        int sA = 1 + 3*i, sB = 2 + 3*i, sC = 3 + 3*i;
        gemm_tiled<CC><<<(BB*MM)/64, 128>>>(xf, W1 + i*CC*CC, t1,
            sumS + sA*CC, sqsS + sA*CC, nullptr, nullptr, nullptr, nullptr, 0.0);

        agg_kernel<<<BB*MM, 128>>>(t1, MM, cent, cent, nbr2, W_pe, 0.2f,
            sumS + sA*CC, sqsS + sA*CC, g1 + i*CC, b1 + i*CC, invM,
            m1b, m2b, gpe, bpe, invK, t2);

        gemm_tiled<CC><<<(BB*MM)/64, 128>>>(t2, W2a + i*CC*CC, xf,
            sumS + sB*CC, sqsS + sB*CC, nullptr, nullptr, nullptr, nullptr, 0.0);

        gemm_tiled<CC><<<(BB*MM)/64, 128>>>(xf, W2b + i*CC*CC, t2,
            sumS + sC*CC, sqsS + sC*CC,
            sumS + sB*CC, sqsS + sB*CC, g2a + i*CC, b2a + i*CC, invM);

        float* dst = (i == LL - 1) ? xf_out : xf;
        resid_kernel<<<(BB*MM*CC)/256, 256>>>(t1, t2,
            sumS + sA*CC, sqsS + sA*CC, g1 + i*CC, b1 + i*CC,
            sumS + sC*CC, sqsS + sC*CC, g2b + i*CC, b2b + i*CC,
            invM, dst, BB*MM*CC);
    }
}

// round 17
// speedup vs baseline: 1.0477x; 1.0477x over previous
#include <cuda_runtime.h>
#include <cstdint>

#define BB 4
#define NN 8192
#define CIN 64
#define CC 128
#define MM 2048
#define KK 32
#define LL 2

typedef unsigned long long ull;

// ---------------- scratch (static device globals; no allocation) ----------------
__device__ float  g_feats[BB*NN*CC];
__device__ float  g_xf[BB*MM*CC];
__device__ float  g_t1[BB*MM*CC];
__device__ float  g_t2[BB*MM*CC];
__device__ float  g_centbuf[BB*MM*3];
__device__ int    g_nbr1[BB*MM*KK];
__device__ int    g_nbr2[BB*MM*KK];
__device__ double g_sumS[7*CC], g_sqsS[7*CC];          // 7 BN stat slots
__device__ double g_m1a[3], g_m2a[6], g_m1b[3], g_m2b[6];

// ---------------- packed f32x2 helpers -------------------------------------------
__device__ __forceinline__ ull pk2(float a, float b) {
    ull r; asm("mov.b64 %0,{%1,%2};" : "=l"(r) : "f"(a), "f"(b)); return r;
}
__device__ __forceinline__ void upk2u(ull v, unsigned& a, unsigned& b) {
    asm("mov.b64 {%0,%1},%2;" : "=r"(a), "=r"(b) : "l"(v));
}
__device__ __forceinline__ ull fma2(ull a, ull b, ull c) {
    ull r; asm("fma.rn.f32x2 %0,%1,%2,%3;" : "=l"(r) : "l"(a), "l"(b), "l"(c)); return r;
}
// warp collectives in ONE instruction (sm_80+)
__device__ __forceinline__ unsigned redux_max(unsigned v) {
    unsigned r; asm("redux.sync.max.u32 %0, %1, 0xffffffff;" : "=r"(r) : "r"(v));
    return r;
}
__device__ __forceinline__ unsigned redux_min(unsigned v) {
    unsigned r; asm("redux.sync.min.u32 %0, %1, 0xffffffff;" : "=r"(r) : "r"(v));
    return r;
}
__device__ __forceinline__ unsigned umin2(unsigned a, unsigned b) { return a < b ? a : b; }
__device__ __forceinline__ unsigned umax2(unsigned a, unsigned b) { return a > b ? a : b; }

// ---------------- inline BN affine reconstruction --------------------------------
__device__ __forceinline__ void bn_aff(const double* __restrict__ sum,
        const double* __restrict__ sqs, const float* __restrict__ gam,
        const float* __restrict__ bet, double inv, int c, float& sc, float& sh) {
    double m = sum[c] * inv;
    double v = sqs[c] * inv - m * m;
    float s = gam[c] * rsqrtf((float)v + 1e-5f);
    sc = s; sh = fmaf(-(float)m, s, bet[c]);
}
__device__ __forceinline__ void bn_aff3(const double* __restrict__ m1,
        const double* __restrict__ m2, const float* __restrict__ W3,
        const float* __restrict__ gam, const float* __restrict__ bet,
        double inv, int c, float& sc, float& sh) {
    double w0 = W3[3*c], w1 = W3[3*c+1], w2 = W3[3*c+2];
    double mean = (m1[0]*w0 + m1[1]*w1 + m1[2]*w2) * inv;
    double e2 = (w0*w0*m2[0] + w1*w1*m2[3] + w2*w2*m2[5]
               + 2.0*(w0*w1*m2[1] + w0*w2*m2[2] + w1*w2*m2[4])) * inv;
    double var = e2 - mean*mean;
    float s = gam[c] * rsqrtf((float)var + 1e-5f);
    sc = s; sh = fmaf(-(float)mean, s, bet[c]);
}

// ---------------- init: zero all accumulators -------------------------------------
__global__ void init_kernel() {
    int t = threadIdx.x;
    for (int i = t; i < 7*CC; i += 1024) { g_sumS[i] = 0.0; g_sqsS[i] = 0.0; }
    if (t < 3) { g_m1a[t] = 0.0; g_m1b[t] = 0.0; }
    if (t < 6) { g_m2a[t] = 0.0; g_m2b[t] = 0.0; }
}

// ------- FPS: exact jax-scan; FFMA2 + integer min/max + paired-REDUX argmax ------
__global__ void __launch_bounds__(1024) fps_kernel(const float* __restrict__ pos,
                                                   float* __restrict__ cent) {
    int b = blockIdx.x, t = threadIdx.x;
    int lane = t & 31, wid = t >> 5;
    const float* P = pos + (size_t)b * NN * 3;

    // 8 strided points per thread (indices t + q*1024), packed into f32x2 pairs
    ull pxp[4], pyp[4], pzp[4];
    unsigned dd[8];                       // distance bit patterns (u32-monotone)
#pragma unroll
    for (int jp = 0; jp < 4; jp++) {
        int i0 = t + (2*jp) * 1024;
        int i1 = t + (2*jp+1) * 1024;
        pxp[jp] = pk2(P[i0*3],   P[i1*3]);
        pyp[jp] = pk2(P[i0*3+1], P[i1*3+1]);
        pzp[jp] = pk2(P[i0*3+2], P[i1*3+2]);
        dd[2*jp] = __float_as_uint(1e10f); dd[2*jp+1] = __float_as_uint(1e10f);
    }

    __shared__ ull red2[2][32];   // per-warp (maxval<<32)|minidx, parity-buffered
    float lx = P[0], ly = P[1], lz = P[2];
    if (t == 0) {
        float* c0 = cent + (size_t)b*MM*3;
        c0[0] = lx; c0[1] = ly; c0[2] = lz;
    }
    const ull ONE2 = pk2(1.0f, 1.0f);

    for (int m = 1; m < MM; m++) {
        int p = m & 1;
        ull nlx2 = pk2(-lx, -lx), nly2 = pk2(-ly, -ly), nlz2 = pk2(-lz, -lz);
#pragma unroll
        for (int jp = 0; jp < 4; jp++) {
            // FFMA2 chain bit-identical to scalar rn sequence:
            // dx=rn(px-lx); sx=rn(dx^2); s=rn(rn(sx+sy)+sz); dd=min(dd,s)
            ull dx = fma2(pxp[jp], ONE2, nlx2);
            ull dy = fma2(pyp[jp], ONE2, nly2);
            ull dz = fma2(pzp[jp], ONE2, nlz2);
            ull sx = fma2(dx, dx, 0ull);
            ull sy = fma2(dy, dy, 0ull);
            ull sz = fma2(dz, dz, 0ull);
            ull s  = fma2(sz, ONE2, fma2(sy, ONE2, sx));
            unsigned u0, u1; upk2u(s, u0, u1);
            dd[2*jp]   = umin2(dd[2*jp],   u0);   // IMNMX, exact (bits monotone)
            dd[2*jp+1] = umin2(dd[2*jp+1], u1);
        }
        // thread-local max value (integer max tree)
        unsigned bm = dd[0];
#pragma unroll
        for (int q = 1; q < 8; q++) bm = umax2(bm, dd[q]);
        // warp max value: one REDUX
        unsigned wmax = redux_max(bm);
        // only threads attaining the warp max scan for their smallest index (rare)
        unsigned cand = 0xffffffffu;
        if (bm == wmax) {
#pragma unroll
            for (int q = 7; q >= 0; q--)
                if (dd[q] == wmax) cand = (unsigned)(t + (q << 10));
        }
        unsigned wmin = redux_min(cand);
        if (lane == 0) red2[p][wid] = ((ull)wmax << 32) | wmin;
        __syncthreads();                            // the ONLY barrier
        // block phase (redundant in every warp): one LDS.64, then two REDUX
        ull wv = red2[p][lane];
        unsigned v32 = (unsigned)(wv >> 32);
        unsigned i32 = (unsigned)wv;
        unsigned bvb = redux_max(v32);
        unsigned candb = (v32 == bvb) ? i32 : 0xffffffffu;
        int sel = (int)redux_min(candb);
        const float* pp = P + (size_t)sel * 3;
        lx = pp[0]; ly = pp[1]; lz = pp[2];         // uniform broadcast load
        if (t == 0) {
            float* co = cent + ((size_t)b*MM + m) * 3;
            co[0] = lx; co[1] = ly; co[2] = lz;
        }
    }
}

// ------- register-tiled GEMM: Y[r,o] = sum_c A[r,c]*W[o,c] ----------------------
template <int CK>
__global__ void __launch_bounds__(128) gemm_tiled(const float* __restrict__ A,
        const float* __restrict__ W, float* __restrict__ Y,
        double* __restrict__ oSum, double* __restrict__ oSqs,
        const double* __restrict__ pSum, const double* __restrict__ pSqs,
        const float* __restrict__ pGam, const float* __restrict__ pBet, double pInv) {
    __shared__ float As[16][68];
    __shared__ float Ws[16][132];
    __shared__ float psc[128], psh[128];
    __shared__ float sred[8][128];
    int t = threadIdx.x;
    int tx = t & 15, ty = t >> 4;
    if (pSum) bn_aff(pSum, pSqs, pGam, pBet, pInv, t, psc[t], psh[t]);
    size_t m0 = (size_t)blockIdx.x * 64;

    float acc[8][8];
#pragma unroll
    for (int i = 0; i < 8; i++)
#pragma unroll
        for (int j = 0; j < 8; j++) acc[i][j] = 0.f;

    for (int k0 = 0; k0 < CK; k0 += 16) {
        __syncthreads();
        {
            int f = t & 3;
            int cbase = k0 + f*4;
#pragma unroll
            for (int p = 0; p < 2; p++) {
                int m = p*32 + (t >> 2);
                float4 v = *(const float4*)(A + (m0 + m)*CK + cbase);
                if (pSum) {
                    v.x = fmaxf(fmaf(v.x, psc[cbase+0], psh[cbase+0]), 0.f);
                    v.y = fmaxf(fmaf(v.y, psc[cbase+1], psh[cbase+1]), 0.f);
                    v.z = fmaxf(fmaf(v.z, psc[cbase+2], psh[cbase+2]), 0.f);
                    v.w = fmaxf(fmaf(v.w, psc[cbase+3], psh[cbase+3]), 0.f);
                }
                As[f*4+0][m] = v.x; As[f*4+1][m] = v.y;
                As[f*4+2][m] = v.z; As[f*4+3][m] = v.w;
            }
        }
        {
            const float* ws = W + (size_t)t*CK + k0;
            float4 w0 = *(const float4*)(ws);
            float4 w1 = *(const float4*)(ws+4);
            float4 w2 = *(const float4*)(ws+8);
            float4 w3 = *(const float4*)(ws+12);
            Ws[ 0][t]=w0.x; Ws[ 1][t]=w0.y; Ws[ 2][t]=w0.z; Ws[ 3][t]=w0.w;
            Ws[ 4][t]=w1.x; Ws[ 5][t]=w1.y; Ws[ 6][t]=w1.z; Ws[ 7][t]=w1.w;
            Ws[ 8][t]=w2.x; Ws[ 9][t]=w2.y; Ws[10][t]=w2.z; Ws[11][t]=w2.w;
            Ws[12][t]=w3.x; Ws[13][t]=w3.y; Ws[14][t]=w3.z; Ws[15][t]=w3.w;
        }
        __syncthreads();
#pragma unroll
        for (int k = 0; k < 16; k++) {
            float a[8], w[8];
            *(float4*)&a[0] = *(const float4*)&As[k][ty*8];
            *(float4*)&a[4] = *(const float4*)&As[k][ty*8+4];
            *(float4*)&w[0] = *(const float4*)&Ws[k][tx*8];
            *(float4*)&w[4] = *(const float4*)&Ws[k][tx*8+4];
#pragma unroll
            for (int i = 0; i < 8; i++)
#pragma unroll
                for (int j = 0; j < 8; j++)
                    acc[i][j] = fmaf(a[i], w[j], acc[i][j]);
        }
    }

#pragma unroll
    for (int i = 0; i < 8; i++) {
        int m = ty*8 + i;
        float* dst = Y + (m0 + m)*128 + tx*8;
        *(float4*)(dst)     = make_float4(acc[i][0], acc[i][1], acc[i][2], acc[i][3]);
        *(float4*)(dst + 4) = make_float4(acc[i][4], acc[i][5], acc[i][6], acc[i][7]);
    }

    float s_[8], q_[8];
#pragma unroll
    for (int j = 0; j < 8; j++) {
        float s = 0.f, q = 0.f;
#pragma unroll
        for (int i = 0; i < 8; i++) {
            s += acc[i][j];
            q = fmaf(acc[i][j], acc[i][j], q);
        }
        s_[j] = s; q_[j] = q;
    }
    __syncthreads();
#pragma unroll
    for (int j = 0; j < 8; j++) sred[ty][tx*8+j] = s_[j];
    __syncthreads();
    float bs = 0.f;
#pragma unroll
    for (int r = 0; r < 8; r++) bs += sred[r][t];
    __syncthreads();
#pragma unroll
    for (int j = 0; j < 8; j++) sred[ty][tx*8+j] = q_[j];
    __syncthreads();
    float bq = 0.f;
#pragma unroll
    for (int r = 0; r < 8; r++) bq += sred[r][t];
    atomicAdd(&oSum[t], (double)bs);
    atomicAdd(&oSqs[t], (double)bq);
}

// ---------------- ball query with smem point cache (exact thresholds) ------------
__global__ void __launch_bounds__(256) bq_kernel(const float* __restrict__ q,
        const float* __restrict__ pts, int np, float r2, int* __restrict__ nbr) {
    extern __shared__ float sp[];
    float* sx = sp; float* sy = sp + np; float* sz = sp + 2*np;
    int gw0 = blockIdx.x * 8;
    int b = gw0 >> 11;
    const float* P = pts + (size_t)b * np * 3;
    for (int idx = threadIdx.x; idx < np*3; idx += 256) {
        float v = P[idx];
        int pt = idx / 3, d = idx - pt*3;
        sp[d*np + pt] = v;
    }
    __syncthreads();
    int w = threadIdx.x >> 5, lane = threadIdx.x & 31;
    int gw = gw0 + w;
    const float* Q = q + (size_t)gw * 3;
    float qx = Q[0], qy = Q[1], qz = Q[2];
    int cnt = 0, first = 0;
    for (int base = 0; base < np; base += 32) {
        int i = base + lane;
        float dx = __fadd_rn(qx, -sx[i]), dy = __fadd_rn(qy, -sy[i]), dz = __fadd_rn(qz, -sz[i]);
        float d2 = __fadd_rn(__fadd_rn(__fmul_rn(dx,dx), __fmul_rn(dy,dy)),
                             __fmul_rn(dz,dz));
        bool pred = d2 < r2;
        unsigned mask = __ballot_sync(0xffffffffu, pred);
        if (cnt == 0 && mask) first = base + __ffs(mask) - 1;
        if (pred) {
            int pos = cnt + __popc(mask & ((1u << lane) - 1u));
            if (pos < KK) nbr[(size_t)gw*KK + pos] = i;
        }
        cnt += __popc(mask);
        if (cnt >= KK) break;
    }
    for (int k = cnt + lane; k < KK; k += 32) nbr[(size_t)gw*KK + k] = first;
}

// ---------------- 3-dim offset moments ------------------------------------------
__global__ void moments_kernel(const int* __restrict__ nbr, const float* __restrict__ pts,
                               const float* __restrict__ cent, float R, int np,
                               double* __restrict__ m1, double* __restrict__ m2) {
    int idx = blockIdx.x * blockDim.x + threadIdx.x;
    int bm = idx / KK;
    int b = bm >> 11;
    int j = nbr[idx];
    float cx = cent[(size_t)bm*3], cy = cent[(size_t)bm*3+1], cz = cent[(size_t)bm*3+2];
    const float* p = pts + ((size_t)b*np + j) * 3;
    float v0 = (p[0]-cx)/R, v1 = (p[1]-cy)/R, v2 = (p[2]-cz)/R;
    double a[9] = { v0, v1, v2,
                    (double)v0*v0, (double)v0*v1, (double)v0*v2,
                    (double)v1*v1, (double)v1*v2, (double)v2*v2 };
#pragma unroll
    for (int v = 0; v < 9; v++) {
        double x = a[v];
        for (int off = 16; off; off >>= 1) x += __shfl_down_sync(0xffffffffu, x, off);
        a[v] = x;
    }
    if ((threadIdx.x & 31) == 0) {
        atomicAdd(&m1[0], a[0]); atomicAdd(&m1[1], a[1]); atomicAdd(&m1[2], a[2]);
        atomicAdd(&m2[0], a[3]); atomicAdd(&m2[1], a[4]); atomicAdd(&m2[2], a[5]);
        atomicAdd(&m2[3], a[6]); atomicAdd(&m2[4], a[7]); atomicAdd(&m2[5], a[8]);
    }
}

// ------- fused gather(+inline feats BN-relu) + pos-conv-BN-relu + max over K -----
__global__ void __launch_bounds__(128) agg_kernel(const float* __restrict__ feats, int np,
        const float* __restrict__ pts, const float* __restrict__ cent,
        const int* __restrict__ nbr, const float* __restrict__ W3, float R,
        const double* __restrict__ fSum, const double* __restrict__ fSqs,
        const float* __restrict__ fGam, const float* __restrict__ fBet, double fInv,
        const double* __restrict__ m1, const double* __restrict__ m2,
        const float* __restrict__ pGam, const float* __restrict__ pBet, double mInv,
        float* __restrict__ out) {
    int bm = blockIdx.x;
    int b = bm >> 11;
    int c = threadIdx.x;
    __shared__ int   sj[KK];
    __shared__ float sg[KK][3];
    if (c < KK) {
        int j = nbr[(size_t)bm*KK + c];
        sj[c] = j;
        float cx = cent[(size_t)bm*3], cy = cent[(size_t)bm*3+1], cz = cent[(size_t)bm*3+2];
        const float* p = pts + ((size_t)b*np + j) * 3;
        sg[c][0] = (p[0]-cx)/R; sg[c][1] = (p[1]-cy)/R; sg[c][2] = (p[2]-cz)/R;
    }
    float asc, ash, sc, sh;
    bn_aff(fSum, fSqs, fGam, fBet, fInv, c, asc, ash);
    bn_aff3(m1, m2, W3, pGam, pBet, mInv, c, sc, sh);
    float w0 = W3[3*c], w1 = W3[3*c+1], w2 = W3[3*c+2];
    __syncthreads();
    const float* F = feats + (size_t)b * np * 128 + c;
    float acc = -3.4e38f;
#pragma unroll
    for (int k = 0; k < KK; k++) {
        float dot = fmaf(w2, sg[k][2], fmaf(w1, sg[k][1], w0 * sg[k][0]));
        float pev = fmaxf(fmaf(sc, dot, sh), 0.f);
        float raw = F[(size_t)sj[k] * 128];
        float gf = fmaxf(fmaf(raw, asc, ash), 0.f);
        acc = fmaxf(acc, gf + pev);
    }
    out[(size_t)bm*128 + c] = acc;
}

// ------ residual: relu( relu(affA(fi)) + affC(y) ), affines inlined --------------
__global__ void resid_kernel(const float* __restrict__ fi, const float* __restrict__ y,
        const double* __restrict__ aSum, const double* __restrict__ aSqs,
        const float* __restrict__ aGam, const float* __restrict__ aBet,
        const double* __restrict__ cSum, const double* __restrict__ cSqs,
        const float* __restrict__ cGam, const float* __restrict__ cBet,
        double inv, float* __restrict__ out, int ntot) {
    int i = blockIdx.x * blockDim.x + threadIdx.x;
    if (i < ntot) {
        int c = i & 127;
        float sa, ha, scc, hc;
        bn_aff(aSum, aSqs, aGam, aBet, inv, c, sa, ha);
        bn_aff(cSum, cSqs, cGam, cBet, inv, c, scc, hc);
        float f = fmaxf(fmaf(fi[i], sa, ha), 0.f);
        out[i] = fmaxf(f + fmaf(y[i], scc, hc), 0.f);
    }
}

// =================================================================================
extern "C" void kernel_launch(void* const* d_in, const int* in_sizes, int n_in,
                              void* d_out, int out_size) {
    const float* pos  = (const float*)d_in[0];
    const float* x    = (const float*)d_in[1];
    const float* W_x  = (const float*)d_in[2];
    const float* gx   = (const float*)d_in[3];
    const float* bx   = (const float*)d_in[4];
    const float* W_ps = (const float*)d_in[5];
    const float* gps  = (const float*)d_in[6];
    const float* bps  = (const float*)d_in[7];
    const float* W_pe = (const float*)d_in[8];
    const float* gpe  = (const float*)d_in[9];
    const float* bpe  = (const float*)d_in[10];
    const float* W1   = (const float*)d_in[11];
    const float* g1   = (const float*)d_in[12];
    const float* b1   = (const float*)d_in[13];
    const float* W2a  = (const float*)d_in[14];
    const float* g2a  = (const float*)d_in[15];
    const float* b2a  = (const float*)d_in[16];
    const float* W2b  = (const float*)d_in[17];
    const float* g2b  = (const float*)d_in[18];
    const float* b2b  = (const float*)d_in[19];

    float* out = (float*)d_out;
    float* cent; float* xf_out; float* centbuf;
    cudaGetSymbolAddress((void**)&centbuf, g_centbuf);
    if (out_size == BB*MM*3 + BB*MM*CC) { cent = out; xf_out = out + BB*MM*3; }
    else                                { cent = centbuf; xf_out = out; }

    float *feats, *xf, *t1, *t2;
    int *nbr1, *nbr2;
    double *sumS, *sqsS, *m1a, *m2a, *m1b, *m2b;
    cudaGetSymbolAddress((void**)&feats, g_feats);
    cudaGetSymbolAddress((void**)&xf,    g_xf);
    cudaGetSymbolAddress((void**)&t1,    g_t1);
    cudaGetSymbolAddress((void**)&t2,    g_t2);
    cudaGetSymbolAddress((void**)&nbr1,  g_nbr1);
    cudaGetSymbolAddress((void**)&nbr2,  g_nbr2);
    cudaGetSymbolAddress((void**)&sumS,  g_sumS);
    cudaGetSymbolAddress((void**)&sqsS,  g_sqsS);
    cudaGetSymbolAddress((void**)&m1a,   g_m1a);
    cudaGetSymbolAddress((void**)&m2a,   g_m2a);
    cudaGetSymbolAddress((void**)&m1b,   g_m1b);
    cudaGetSymbolAddress((void**)&m2b,   g_m2b);

    static cudaStream_t s1 = nullptr, s2 = nullptr;
    static cudaEvent_t eFork, eXmlp, eFps, eS2;
    if (!s1) {
        cudaStreamCreateWithFlags(&s1, cudaStreamNonBlocking);
        cudaStreamCreateWithFlags(&s2, cudaStreamNonBlocking);
        cudaEventCreateWithFlags(&eFork, cudaEventDisableTiming);
        cudaEventCreateWithFlags(&eXmlp, cudaEventDisableTiming);
        cudaEventCreateWithFlags(&eFps,  cudaEventDisableTiming);
        cudaEventCreateWithFlags(&eS2,   cudaEventDisableTiming);
    }

    const int smemBQ1 = NN * 3 * 4;
    const int smemBQ2 = MM * 3 * 4;
    cudaFuncSetAttribute(bq_kernel, cudaFuncAttributeMaxDynamicSharedMemorySize, smemBQ1);

    const double invN = 1.0 / (BB*NN);
    const double invM = 1.0 / (BB*MM);
    const double invK = 1.0 / (BB*MM*KK);

    // init, then fork x_mlp chain onto s1 while FPS runs on default
    init_kernel<<<1, 1024>>>();
    cudaEventRecord(eFork, 0);
    cudaStreamWaitEvent(s1, eFork, 0);

    fps_kernel<<<BB, 1024>>>(pos, cent);

    gemm_tiled<CIN><<<(BB*NN)/64, 128, 0, s1>>>(x, W_x, feats,
        sumS + 0*CC, sqsS + 0*CC, nullptr, nullptr, nullptr, nullptr, 0.0);
    cudaEventRecord(eXmlp, s1);

    // fork bq2+momentsB onto s2 (needs cent only)
    cudaEventRecord(eFps, 0);
    cudaStreamWaitEvent(s2, eFps, 0);
    bq_kernel<<<(BB*MM)/8, 256, smemBQ2, s2>>>(cent, cent, MM, 0.04f, nbr2);
    moments_kernel<<<(BB*MM*KK)/256, 256, 0, s2>>>(nbr2, cent, cent, 0.2f, MM, m1b, m2b);
    cudaEventRecord(eS2, s2);

    // default: bq1 + momentsA
    bq_kernel<<<(BB*MM)/8, 256, smemBQ1>>>(cent, pos, NN, 0.01f, nbr1);
    moments_kernel<<<(BB*MM*KK)/256, 256>>>(nbr1, pos, cent, 0.1f, NN, m1a, m2a);

    cudaStreamWaitEvent(0, eS2, 0);
    cudaStreamWaitEvent(0, eXmlp, 0);

    // stage-1 aggregation (all BN affines inlined) -> xf
    agg_kernel<<<BB*MM, 128>>>(feats, NN, pos, cent, nbr1, W_ps, 0.1f,
        sumS + 0*CC, sqsS + 0*CC, gx, bx, invN,
        m1a, m2a, gps, bps, invK, xf);

    // InvResMLP blocks
    for (int i = 0; i < LL; i++) {
        int sA = 1 + 3*i, sB = 2 + 3*i, sC = 3 + 3*i;
        gemm_tiled<CC><<<(BB*MM)/64, 128>>>(xf, W1 + i*CC*CC, t1,
            sumS + sA*CC, sqsS + sA*CC, nullptr, nullptr, nullptr, nullptr, 0.0);

        agg_kernel<<<BB*MM, 128>>>(t1, MM, cent, cent, nbr2, W_pe, 0.2f,
            sumS + sA*CC, sqsS + sA*CC, g1 + i*CC, b1 + i*CC, invM,
            m1b, m2b, gpe, bpe, invK, t2);

        gemm_tiled<CC><<<(BB*MM)/64, 128>>>(t2, W2a + i*CC*CC, xf,
            sumS + sB*CC, sqsS + sB*CC, nullptr, nullptr, nullptr, nullptr, 0.0);

        gemm_tiled<CC><<<(BB*MM)/64, 128>>>(xf, W2b + i*CC*CC, t2,
            sumS + sC*CC, sqsS + sC*CC,
            sumS + sB*CC, sqsS + sB*CC, g2a + i*CC, b2a + i*CC, invM);

        float* dst = (i == LL - 1) ? xf_out : xf;
        resid_kernel<<<(BB*MM*CC)/256, 256>>>(t1, t2,
            sumS + sA*CC, sqsS + sA*CC, g1 + i*CC, b1 + i*CC,
            sumS + sC*CC, sqsS + sC*CC, g2b + i*CC, b2b + i*CC,
            invM, dst, BB*MM*CC);
    }
}